// round 1
// baseline (speedup 1.0000x reference)
#include <cuda_runtime.h>
#include <math.h>

#define N_ENTITY 64368
#define N_REL 40
#define DIM 128
#define N_BASES 8
#define N_EDGES 500000
#define BATCH 64
#define SEED_LEN 32

// Scratch (allocation-free rule: __device__ globals)
__device__ float g_agg[(size_t)N_ENTITY * DIM];   // agg, then nodes in-place
__device__ float g_deg[N_ENTITY];
__device__ float g_u[BATCH * DIM];

// ---------------------------------------------------------------------------
// Stage 0: zero agg + deg
// ---------------------------------------------------------------------------
__global__ void zero_kernel() {
    size_t i = (size_t)blockIdx.x * blockDim.x + threadIdx.x;
    size_t total4 = ((size_t)N_ENTITY * DIM) / 4;
    if (i < total4) {
        ((float4*)g_agg)[i] = make_float4(0.f, 0.f, 0.f, 0.f);
    }
    if (i < N_ENTITY) g_deg[i] = 0.f;
}

// ---------------------------------------------------------------------------
// Stage 1: edge aggregation. One warp per edge, lane handles 4 dims (float4).
// message m = sum_b att[type,b] * basis[b, src, :]; red-add into agg[dst].
// ---------------------------------------------------------------------------
__global__ void edge_kernel(const int* __restrict__ src,
                            const int* __restrict__ dst,
                            const int* __restrict__ typ,
                            const float* __restrict__ basis,
                            const float* __restrict__ att) {
    __shared__ float att_s[N_REL * N_BASES];
    for (int i = threadIdx.x; i < N_REL * N_BASES; i += blockDim.x)
        att_s[i] = att[i];
    __syncthreads();

    int e = (int)((blockIdx.x * blockDim.x + threadIdx.x) >> 5);
    int lane = threadIdx.x & 31;
    if (e >= N_EDGES) return;

    int s = src[e];
    int d = dst[e];
    int t = typ[e];

    float4 acc = make_float4(0.f, 0.f, 0.f, 0.f);
#pragma unroll
    for (int b = 0; b < N_BASES; b++) {
        float c = att_s[t * N_BASES + b];
        const float4* row =
            (const float4*)(basis + ((size_t)b * N_ENTITY + (size_t)s) * DIM);
        float4 v = __ldg(row + lane);
        acc.x = fmaf(c, v.x, acc.x);
        acc.y = fmaf(c, v.y, acc.y);
        acc.z = fmaf(c, v.z, acc.z);
        acc.w = fmaf(c, v.w, acc.w);
    }

    float* outp = g_agg + (size_t)d * DIM + lane * 4;
    asm volatile("red.global.add.v4.f32 [%0], {%1, %2, %3, %4};"
                 :: "l"(outp), "f"(acc.x), "f"(acc.y), "f"(acc.z), "f"(acc.w)
                 : "memory");

    if (lane == 0) atomicAdd(&g_deg[d], 1.0f);
}

// ---------------------------------------------------------------------------
// Stage 2: nodes = agg / max(deg,1) + root + bias   (in-place into g_agg)
// ---------------------------------------------------------------------------
__global__ void finalize_kernel(const float* __restrict__ root,
                                const float* __restrict__ bias) {
    size_t i = (size_t)blockIdx.x * blockDim.x + threadIdx.x;  // float4 index
    size_t total4 = ((size_t)N_ENTITY * DIM) / 4;
    if (i >= total4) return;
    int node = (int)(i / (DIM / 4));
    int d4 = (int)(i % (DIM / 4));
    float invdeg = 1.0f / fmaxf(g_deg[node], 1.0f);
    float4 a = ((float4*)g_agg)[i];
    float4 r = ((const float4*)root)[i];
    const float4 bb = ((const float4*)bias)[d4];
    a.x = a.x * invdeg + r.x + bb.x;
    a.y = a.y * invdeg + r.y + bb.y;
    a.z = a.z * invdeg + r.z + bb.z;
    a.w = a.w * invdeg + r.w + bb.w;
    ((float4*)g_agg)[i] = a;
}

// ---------------------------------------------------------------------------
// Stage 3: attention pooling. One block per batch item, 128 threads (=DIM).
// e[s] = sum_d tanh( (H @ A)[s,d] ) * bvec[d]; softmax; u = attn @ H
// ---------------------------------------------------------------------------
__global__ void attn_kernel(const int* __restrict__ seed_ids,
                            const float* __restrict__ A,
                            const float* __restrict__ bvec) {
    __shared__ float H[SEED_LEN][DIM];
    __shared__ float part[4][SEED_LEN];
    __shared__ float attnw[SEED_LEN];

    int b = blockIdx.x;
    int tid = threadIdx.x;  // = output dim index

    // gather H
    for (int idx = tid; idx < SEED_LEN * DIM; idx += DIM) {
        int s = idx / DIM, d = idx % DIM;
        int node = seed_ids[b * SEED_LEN + s];
        H[s][d] = g_agg[(size_t)node * DIM + d];
    }
    __syncthreads();

    // acc[s] = sum_k H[s][k] * A[k][tid]
    float acc[SEED_LEN];
#pragma unroll
    for (int s = 0; s < SEED_LEN; s++) acc[s] = 0.f;
    for (int k = 0; k < DIM; k++) {
        float a = A[k * DIM + tid];
#pragma unroll
        for (int s = 0; s < SEED_LEN; s++) acc[s] = fmaf(H[s][k], a, acc[s]);
    }

    float bd = bvec[tid];
    int lane = tid & 31, warp = tid >> 5;
#pragma unroll
    for (int s = 0; s < SEED_LEN; s++) {
        float v = tanhf(acc[s]) * bd;
#pragma unroll
        for (int o = 16; o > 0; o >>= 1) v += __shfl_xor_sync(0xffffffffu, v, o);
        if (lane == 0) part[warp][s] = v;
    }
    __syncthreads();

    if (tid < SEED_LEN) {  // exactly warp 0
        float ev = part[0][tid] + part[1][tid] + part[2][tid] + part[3][tid];
        float m = ev;
#pragma unroll
        for (int o = 16; o > 0; o >>= 1)
            m = fmaxf(m, __shfl_xor_sync(0xffffffffu, m, o));
        float ex = expf(ev - m);
        float ss = ex;
#pragma unroll
        for (int o = 16; o > 0; o >>= 1) ss += __shfl_xor_sync(0xffffffffu, ss, o);
        attnw[tid] = ex / ss;
    }
    __syncthreads();

    float u = 0.f;
#pragma unroll
    for (int s = 0; s < SEED_LEN; s++) u = fmaf(attnw[s], H[s][tid], u);
    g_u[b * DIM + tid] = u;
}

// ---------------------------------------------------------------------------
// Stage 4: scores[b, n] = sum_d u[b,d] * nodes[n,d] + out_bias[n]
// Block = 64 entities x 64 batches; 256 threads, 4x4 register tiles.
// ---------------------------------------------------------------------------
#define ETILE 64
#define KCH 64
__global__ void scores_kernel(const float* __restrict__ out_bias,
                              float* __restrict__ out) {
    __shared__ float nS[ETILE][KCH + 1];
    __shared__ float uS[BATCH][KCH + 1];
    int e0 = blockIdx.x * ETILE;
    int tid = threadIdx.x;
    int ti = tid & 15;   // entity group
    int tj = tid >> 4;   // batch group

    float acc[4][4];
#pragma unroll
    for (int i = 0; i < 4; i++)
#pragma unroll
        for (int j = 0; j < 4; j++) acc[i][j] = 0.f;

    for (int kc = 0; kc < DIM; kc += KCH) {
        __syncthreads();
        for (int idx = tid; idx < ETILE * KCH; idx += 256) {
            int r = idx / KCH, c = idx % KCH;
            int e = e0 + r;
            nS[r][c] = (e < N_ENTITY) ? g_agg[(size_t)e * DIM + kc + c] : 0.f;
            uS[r][c] = g_u[r * DIM + kc + c];
        }
        __syncthreads();
#pragma unroll 8
        for (int k = 0; k < KCH; k++) {
            float nf[4], uf[4];
#pragma unroll
            for (int i = 0; i < 4; i++) nf[i] = nS[ti * 4 + i][k];
#pragma unroll
            for (int j = 0; j < 4; j++) uf[j] = uS[tj * 4 + j][k];
#pragma unroll
            for (int i = 0; i < 4; i++)
#pragma unroll
                for (int j = 0; j < 4; j++)
                    acc[i][j] = fmaf(nf[i], uf[j], acc[i][j]);
        }
    }

#pragma unroll
    for (int i = 0; i < 4; i++) {
        int e = e0 + ti * 4 + i;
        if (e >= N_ENTITY) continue;
        float ob = out_bias[e];
#pragma unroll
        for (int j = 0; j < 4; j++) {
            int bb = tj * 4 + j;
            out[(size_t)bb * N_ENTITY + e] = acc[i][j] + ob;
        }
    }
}

// ---------------------------------------------------------------------------
extern "C" void kernel_launch(void* const* d_in, const int* in_sizes, int n_in,
                              void* d_out, int out_size) {
    const int*   seed_ids = (const int*)d_in[0];
    const int*   edge_src = (const int*)d_in[1];
    const int*   edge_dst = (const int*)d_in[2];
    const int*   edge_typ = (const int*)d_in[3];
    const float* basis    = (const float*)d_in[4];
    const float* att      = (const float*)d_in[5];
    const float* root     = (const float*)d_in[6];
    const float* rbias    = (const float*)d_in[7];
    const float* attn_a   = (const float*)d_in[8];
    const float* attn_b   = (const float*)d_in[9];
    const float* out_bias = (const float*)d_in[10];
    float* out = (float*)d_out;

    // Stage 0: zero
    {
        size_t total4 = ((size_t)N_ENTITY * DIM) / 4;  // 2,059,776
        int blocks = (int)((total4 + 255) / 256);
        zero_kernel<<<blocks, 256>>>();
    }
    // Stage 1: edges (1 warp per edge; 8 edges per 256-thread block)
    {
        int blocks = N_EDGES / 8;  // 62500, exact
        edge_kernel<<<blocks, 256>>>(edge_src, edge_dst, edge_typ, basis, att);
    }
    // Stage 2: finalize nodes in-place
    {
        size_t total4 = ((size_t)N_ENTITY * DIM) / 4;
        int blocks = (int)((total4 + 255) / 256);
        finalize_kernel<<<blocks, 256>>>(root, rbias);
    }
    // Stage 3: attention pooling -> g_u
    attn_kernel<<<BATCH, DIM>>>(seed_ids, attn_a, attn_b);

    // Stage 4: scores
    {
        int blocks = (N_ENTITY + ETILE - 1) / ETILE;  // 1006
        scores_kernel<<<blocks, 256>>>(out_bias, out);
    }
}

// round 2
// speedup vs baseline: 2.0154x; 2.0154x over previous
#include <cuda_runtime.h>
#include <math.h>

#define N_ENTITY 64368
#define N_REL 40
#define DIM 128
#define N_BASES 8
#define N_EDGES 500000
#define BATCH 64
#define SEED_LEN 32

#define SCAN_BLK 1024
#define SCAN_NBLK 63            // 63*1024 = 64512 >= 64368
#define HIST_PAD (SCAN_NBLK * SCAN_BLK)

// ------------------------- device scratch (no allocs) ----------------------
__device__ float g_agg[(size_t)N_ENTITY * DIM];   // agg, then nodes in-place
__device__ float g_deg[N_ENTITY];
__device__ float g_u[BATCH * DIM];
__device__ int   g_hist[HIST_PAD];     // edge count per src
__device__ int   g_start[HIST_PAD];    // per-chunk exclusive scan
__device__ int   g_boff[SCAN_NBLK];    // chunk offsets
__device__ int   g_bsum[SCAN_NBLK];
__device__ int   g_cursor[N_ENTITY];
__device__ int   g_pack[N_EDGES];      // dst | (type<<20), grouped by src

// ---------------------------------------------------------------------------
// Stage 0: zero everything that needs it
// ---------------------------------------------------------------------------
__global__ void zero_kernel() {
    size_t i = (size_t)blockIdx.x * blockDim.x + threadIdx.x;
    size_t total4 = ((size_t)N_ENTITY * DIM) / 4;
    if (i < total4) ((float4*)g_agg)[i] = make_float4(0.f, 0.f, 0.f, 0.f);
    if (i < HIST_PAD) g_hist[i] = 0;
    if (i < N_ENTITY) { g_deg[i] = 0.f; g_cursor[i] = 0; }
}

// ---------------------------------------------------------------------------
// Stage 1a: histogram of src + degree of dst
// ---------------------------------------------------------------------------
__global__ void hist_kernel(const int* __restrict__ src,
                            const int* __restrict__ dst) {
    int e = blockIdx.x * blockDim.x + threadIdx.x;
    if (e >= N_EDGES) return;
    atomicAdd(&g_hist[src[e]], 1);
    atomicAdd(&g_deg[dst[e]], 1.0f);
}

// ---------------------------------------------------------------------------
// Stage 1b: per-chunk exclusive scan (Hillis-Steele), chunk = 1024
// ---------------------------------------------------------------------------
__global__ void scan1_kernel() {
    __shared__ int buf[SCAN_BLK];
    int t = threadIdx.x;
    int i = blockIdx.x * SCAN_BLK + t;
    int v = g_hist[i];
    buf[t] = v;
    __syncthreads();
#pragma unroll
    for (int off = 1; off < SCAN_BLK; off <<= 1) {
        int tmp = (t >= off) ? buf[t - off] : 0;
        __syncthreads();
        buf[t] += tmp;
        __syncthreads();
    }
    g_start[i] = buf[t] - v;  // exclusive
    if (t == SCAN_BLK - 1) g_bsum[blockIdx.x] = buf[t];
}

__global__ void scan2_kernel() {
    __shared__ int buf[64];
    int t = threadIdx.x;   // 64 threads
    buf[t] = (t < SCAN_NBLK) ? g_bsum[t] : 0;
    __syncthreads();
#pragma unroll
    for (int off = 1; off < 64; off <<= 1) {
        int tmp = (t >= off) ? buf[t - off] : 0;
        __syncthreads();
        buf[t] += tmp;
        __syncthreads();
    }
    if (t < SCAN_NBLK) g_boff[t] = buf[t] - g_bsum[t];  // exclusive
}

// ---------------------------------------------------------------------------
// Stage 1c: scatter edges grouped by src (order within group irrelevant)
// ---------------------------------------------------------------------------
__global__ void scatter_kernel(const int* __restrict__ src,
                               const int* __restrict__ dst,
                               const int* __restrict__ typ) {
    int e = blockIdx.x * blockDim.x + threadIdx.x;
    if (e >= N_EDGES) return;
    int s = src[e];
    int pos = g_start[s] + g_boff[s >> 10] + atomicAdd(&g_cursor[s], 1);
    g_pack[pos] = dst[e] | (typ[e] << 20);
}

// ---------------------------------------------------------------------------
// Stage 2: grouped aggregation. One warp per src entity; the 8 basis rows
// are loaded ONCE into registers, then all edges of this src stream through.
// ---------------------------------------------------------------------------
__global__ void agg_kernel(const float* __restrict__ basis,
                           const float* __restrict__ att) {
    __shared__ float4 att_s[N_REL * 2];   // 40 rels x 8 coeffs as 2 float4
    for (int i = threadIdx.x; i < N_REL * 2; i += blockDim.x)
        att_s[i] = ((const float4*)att)[i];
    __syncthreads();

    int w = (int)((blockIdx.x * blockDim.x + threadIdx.x) >> 5);
    int lane = threadIdx.x & 31;
    if (w >= N_ENTITY) return;
    int cnt = g_hist[w];
    if (cnt == 0) return;
    int start = g_start[w] + g_boff[w >> 10];

    float4 r[N_BASES];
#pragma unroll
    for (int b = 0; b < N_BASES; b++)
        r[b] = __ldg((const float4*)(basis + ((size_t)b * N_ENTITY + (size_t)w) * DIM) + lane);

    for (int i0 = 0; i0 < cnt; i0 += 32) {
        int n = min(32, cnt - i0);
        int pk = 0;
        if (lane < n) pk = g_pack[start + i0 + lane];
        for (int i = 0; i < n; i++) {
            int p = __shfl_sync(0xffffffffu, pk, i);
            int d = p & 0xFFFFF;
            int t = p >> 20;
            float4 c0 = att_s[t * 2 + 0];
            float4 c1 = att_s[t * 2 + 1];
            float4 acc;
            acc.x = c0.x * r[0].x; acc.y = c0.x * r[0].y;
            acc.z = c0.x * r[0].z; acc.w = c0.x * r[0].w;
            acc.x = fmaf(c0.y, r[1].x, acc.x); acc.y = fmaf(c0.y, r[1].y, acc.y);
            acc.z = fmaf(c0.y, r[1].z, acc.z); acc.w = fmaf(c0.y, r[1].w, acc.w);
            acc.x = fmaf(c0.z, r[2].x, acc.x); acc.y = fmaf(c0.z, r[2].y, acc.y);
            acc.z = fmaf(c0.z, r[2].z, acc.z); acc.w = fmaf(c0.z, r[2].w, acc.w);
            acc.x = fmaf(c0.w, r[3].x, acc.x); acc.y = fmaf(c0.w, r[3].y, acc.y);
            acc.z = fmaf(c0.w, r[3].z, acc.z); acc.w = fmaf(c0.w, r[3].w, acc.w);
            acc.x = fmaf(c1.x, r[4].x, acc.x); acc.y = fmaf(c1.x, r[4].y, acc.y);
            acc.z = fmaf(c1.x, r[4].z, acc.z); acc.w = fmaf(c1.x, r[4].w, acc.w);
            acc.x = fmaf(c1.y, r[5].x, acc.x); acc.y = fmaf(c1.y, r[5].y, acc.y);
            acc.z = fmaf(c1.y, r[5].z, acc.z); acc.w = fmaf(c1.y, r[5].w, acc.w);
            acc.x = fmaf(c1.z, r[6].x, acc.x); acc.y = fmaf(c1.z, r[6].y, acc.y);
            acc.z = fmaf(c1.z, r[6].z, acc.z); acc.w = fmaf(c1.z, r[6].w, acc.w);
            acc.x = fmaf(c1.w, r[7].x, acc.x); acc.y = fmaf(c1.w, r[7].y, acc.y);
            acc.z = fmaf(c1.w, r[7].z, acc.z); acc.w = fmaf(c1.w, r[7].w, acc.w);

            float* outp = g_agg + (size_t)d * DIM + lane * 4;
            asm volatile("red.global.add.v4.f32 [%0], {%1, %2, %3, %4};"
                         :: "l"(outp), "f"(acc.x), "f"(acc.y), "f"(acc.z), "f"(acc.w)
                         : "memory");
        }
    }
}

// ---------------------------------------------------------------------------
// Stage 3: nodes = agg / max(deg,1) + root + bias   (in-place into g_agg)
// ---------------------------------------------------------------------------
__global__ void finalize_kernel(const float* __restrict__ root,
                                const float* __restrict__ bias) {
    size_t i = (size_t)blockIdx.x * blockDim.x + threadIdx.x;  // float4 index
    size_t total4 = ((size_t)N_ENTITY * DIM) / 4;
    if (i >= total4) return;
    int node = (int)(i / (DIM / 4));
    int d4 = (int)(i % (DIM / 4));
    float invdeg = 1.0f / fmaxf(g_deg[node], 1.0f);
    float4 a = ((float4*)g_agg)[i];
    float4 r = ((const float4*)root)[i];
    const float4 bb = ((const float4*)bias)[d4];
    a.x = a.x * invdeg + r.x + bb.x;
    a.y = a.y * invdeg + r.y + bb.y;
    a.z = a.z * invdeg + r.z + bb.z;
    a.w = a.w * invdeg + r.w + bb.w;
    ((float4*)g_agg)[i] = a;
}

// ---------------------------------------------------------------------------
// Stage 4: attention pooling. One block per batch item, 256 threads (8 warps).
// Warp w computes rows (seeds) 4w..4w+3 of tanh(H@A); A read through L1.
// ---------------------------------------------------------------------------
__global__ void attn_kernel(const int* __restrict__ seed_ids,
                            const float* __restrict__ A,
                            const float* __restrict__ bvec) {
    __shared__ float H[SEED_LEN][DIM + 1];
    __shared__ float e_s[SEED_LEN];
    __shared__ float attnw[SEED_LEN];

    int b = blockIdx.x;
    int tid = threadIdx.x;
    int lane = tid & 31, warp = tid >> 5;

    // gather H [32 x 128]
    for (int r = 0; r < SEED_LEN * DIM / 256; r++) {
        int idx = r * 256 + tid;
        int s = idx >> 7, d = idx & 127;
        int node = seed_ids[b * SEED_LEN + s];
        H[s][d] = g_agg[(size_t)node * DIM + d];
    }
    __syncthreads();

    // acc[ss][j]: seed 4*warp+ss, dim 4*lane+j
    float4 acc[4];
#pragma unroll
    for (int ss = 0; ss < 4; ss++) acc[ss] = make_float4(0.f, 0.f, 0.f, 0.f);
    int s0 = warp * 4;
#pragma unroll 4
    for (int k = 0; k < DIM; k++) {
        float4 a4 = __ldg((const float4*)(A + (size_t)k * DIM) + lane);
        float h0 = H[s0 + 0][k];
        float h1 = H[s0 + 1][k];
        float h2 = H[s0 + 2][k];
        float h3 = H[s0 + 3][k];
        acc[0].x = fmaf(h0, a4.x, acc[0].x); acc[0].y = fmaf(h0, a4.y, acc[0].y);
        acc[0].z = fmaf(h0, a4.z, acc[0].z); acc[0].w = fmaf(h0, a4.w, acc[0].w);
        acc[1].x = fmaf(h1, a4.x, acc[1].x); acc[1].y = fmaf(h1, a4.y, acc[1].y);
        acc[1].z = fmaf(h1, a4.z, acc[1].z); acc[1].w = fmaf(h1, a4.w, acc[1].w);
        acc[2].x = fmaf(h2, a4.x, acc[2].x); acc[2].y = fmaf(h2, a4.y, acc[2].y);
        acc[2].z = fmaf(h2, a4.z, acc[2].z); acc[2].w = fmaf(h2, a4.w, acc[2].w);
        acc[3].x = fmaf(h3, a4.x, acc[3].x); acc[3].y = fmaf(h3, a4.y, acc[3].y);
        acc[3].z = fmaf(h3, a4.z, acc[3].z); acc[3].w = fmaf(h3, a4.w, acc[3].w);
    }

    float4 b4 = __ldg((const float4*)bvec + lane);
#pragma unroll
    for (int ss = 0; ss < 4; ss++) {
        float v = tanhf(acc[ss].x) * b4.x + tanhf(acc[ss].y) * b4.y +
                  tanhf(acc[ss].z) * b4.z + tanhf(acc[ss].w) * b4.w;
#pragma unroll
        for (int o = 16; o > 0; o >>= 1) v += __shfl_xor_sync(0xffffffffu, v, o);
        if (lane == 0) e_s[s0 + ss] = v;
    }
    __syncthreads();

    if (warp == 0) {  // softmax over the 32 seeds
        float ev = e_s[lane];
        float m = ev;
#pragma unroll
        for (int o = 16; o > 0; o >>= 1)
            m = fmaxf(m, __shfl_xor_sync(0xffffffffu, m, o));
        float ex = expf(ev - m);
        float ss2 = ex;
#pragma unroll
        for (int o = 16; o > 0; o >>= 1) ss2 += __shfl_xor_sync(0xffffffffu, ss2, o);
        attnw[lane] = ex / ss2;
    }
    __syncthreads();

    if (tid < DIM) {
        float u = 0.f;
#pragma unroll
        for (int s = 0; s < SEED_LEN; s++) u = fmaf(attnw[s], H[s][tid], u);
        g_u[b * DIM + tid] = u;
    }
}

// ---------------------------------------------------------------------------
// Stage 5: scores[b, n] = sum_d u[b,d] * nodes[n,d] + out_bias[n]
// ---------------------------------------------------------------------------
#define ETILE 64
#define KCH 64
__global__ void scores_kernel(const float* __restrict__ out_bias,
                              float* __restrict__ out) {
    __shared__ float nS[ETILE][KCH + 1];
    __shared__ float uS[BATCH][KCH + 1];
    int e0 = blockIdx.x * ETILE;
    int tid = threadIdx.x;
    int ti = tid & 15;   // entity group
    int tj = tid >> 4;   // batch group

    float acc[4][4];
#pragma unroll
    for (int i = 0; i < 4; i++)
#pragma unroll
        for (int j = 0; j < 4; j++) acc[i][j] = 0.f;

    for (int kc = 0; kc < DIM; kc += KCH) {
        __syncthreads();
        for (int idx = tid; idx < ETILE * KCH; idx += 256) {
            int r = idx / KCH, c = idx % KCH;
            int e = e0 + r;
            nS[r][c] = (e < N_ENTITY) ? g_agg[(size_t)e * DIM + kc + c] : 0.f;
            uS[r][c] = g_u[r * DIM + kc + c];
        }
        __syncthreads();
#pragma unroll 8
        for (int k = 0; k < KCH; k++) {
            float nf[4], uf[4];
#pragma unroll
            for (int i = 0; i < 4; i++) nf[i] = nS[ti * 4 + i][k];
#pragma unroll
            for (int j = 0; j < 4; j++) uf[j] = uS[tj * 4 + j][k];
#pragma unroll
            for (int i = 0; i < 4; i++)
#pragma unroll
                for (int j = 0; j < 4; j++)
                    acc[i][j] = fmaf(nf[i], uf[j], acc[i][j]);
        }
    }

#pragma unroll
    for (int i = 0; i < 4; i++) {
        int e = e0 + ti * 4 + i;
        if (e >= N_ENTITY) continue;
        float ob = out_bias[e];
#pragma unroll
        for (int j = 0; j < 4; j++) {
            int bb = tj * 4 + j;
            out[(size_t)bb * N_ENTITY + e] = acc[i][j] + ob;
        }
    }
}

// ---------------------------------------------------------------------------
extern "C" void kernel_launch(void* const* d_in, const int* in_sizes, int n_in,
                              void* d_out, int out_size) {
    const int*   seed_ids = (const int*)d_in[0];
    const int*   edge_src = (const int*)d_in[1];
    const int*   edge_dst = (const int*)d_in[2];
    const int*   edge_typ = (const int*)d_in[3];
    const float* basis    = (const float*)d_in[4];
    const float* att      = (const float*)d_in[5];
    const float* root     = (const float*)d_in[6];
    const float* rbias    = (const float*)d_in[7];
    const float* attn_a   = (const float*)d_in[8];
    const float* attn_b   = (const float*)d_in[9];
    const float* out_bias = (const float*)d_in[10];
    float* out = (float*)d_out;

    size_t total4 = ((size_t)N_ENTITY * DIM) / 4;
    int zblocks = (int)((total4 + 255) / 256);
    zero_kernel<<<zblocks, 256>>>();

    hist_kernel<<<(N_EDGES + 255) / 256, 256>>>(edge_src, edge_dst);
    scan1_kernel<<<SCAN_NBLK, SCAN_BLK>>>();
    scan2_kernel<<<1, 64>>>();
    scatter_kernel<<<(N_EDGES + 255) / 256, 256>>>(edge_src, edge_dst, edge_typ);

    {
        int nwarps = N_ENTITY;
        int blocks = (nwarps * 32 + 255) / 256;
        agg_kernel<<<blocks, 256>>>(basis, att);
    }

    finalize_kernel<<<zblocks, 256>>>(root, rbias);
    attn_kernel<<<BATCH, 256>>>(seed_ids, attn_a, attn_b);
    scores_kernel<<<(N_ENTITY + ETILE - 1) / ETILE, 256>>>(out_bias, out);
}

// round 4
// speedup vs baseline: 2.0465x; 1.0154x over previous
#include <cuda_runtime.h>
#include <math.h>

#define N_ENTITY 64368
#define N_REL 40
#define DIM 128
#define N_BASES 8
#define N_EDGES 500000
#define BATCH 64
#define SEED_LEN 32

#define SCAN_BLK 1024
#define SCAN_NBLK 63            // 63*1024 = 64512 >= 64368
#define HIST_PAD (SCAN_NBLK * SCAN_BLK)

// ------------------------- device scratch (no allocs) ----------------------
__device__ float g_agg[(size_t)N_ENTITY * DIM];
__device__ float g_deg[N_ENTITY];
__device__ float g_u[BATCH * DIM];
__device__ int   g_hist[HIST_PAD];     // edge count per src
__device__ int   g_start[HIST_PAD];    // group start (contiguous, arbitrary order)
__device__ int   g_cursor[N_ENTITY];
__device__ int   g_total;
__device__ int   g_pack[N_EDGES];      // dst | (type<<20), grouped by src

// ---------------------------------------------------------------------------
// 1) zero metadata (hist/deg/cursor/total)
// ---------------------------------------------------------------------------
__global__ void zero_meta_kernel() {
    int i = blockIdx.x * blockDim.x + threadIdx.x;
    if (i < HIST_PAD) g_hist[i] = 0;
    if (i < N_ENTITY) { g_deg[i] = 0.f; g_cursor[i] = 0; }
    if (i == 0) g_total = 0;
}

// ---------------------------------------------------------------------------
// 2) histogram of src + degree of dst
// ---------------------------------------------------------------------------
__global__ void hist_kernel(const int* __restrict__ src,
                            const int* __restrict__ dst) {
    int e = blockIdx.x * blockDim.x + threadIdx.x;
    if (e >= N_EDGES) return;
    atomicAdd(&g_hist[src[e]], 1);
    atomicAdd(&g_deg[dst[e]], 1.0f);
}

// ---------------------------------------------------------------------------
// 3) single-pass offset allocation: block scan (shfl) + atomic block base.
//    Group ORDER across blocks is arbitrary — only contiguity matters.
// ---------------------------------------------------------------------------
__global__ void scan_kernel() {
    __shared__ int wsum[32];
    __shared__ int base_s;
    int t = threadIdx.x;
    int lane = t & 31, warp = t >> 5;
    int i = blockIdx.x * SCAN_BLK + t;
    int v = g_hist[i];

    // warp inclusive scan
    int x = v;
#pragma unroll
    for (int o = 1; o < 32; o <<= 1) {
        int y = __shfl_up_sync(0xffffffffu, x, o);
        if (lane >= o) x += y;
    }
    if (lane == 31) wsum[warp] = x;
    __syncthreads();
    if (warp == 0) {
        int s = wsum[lane];
#pragma unroll
        for (int o = 1; o < 32; o <<= 1) {
            int y = __shfl_up_sync(0xffffffffu, s, o);
            if (lane >= o) s += y;
        }
        wsum[lane] = s;  // inclusive over warp sums
    }
    __syncthreads();
    int incl = x + (warp ? wsum[warp - 1] : 0);
    if (t == SCAN_BLK - 1) base_s = atomicAdd(&g_total, incl);
    __syncthreads();
    g_start[i] = base_s + incl - v;  // exclusive + block base
}

// ---------------------------------------------------------------------------
// 4) zero g_agg (33 MB) — placed here so agg_kernel is launch #6 for ncu
// ---------------------------------------------------------------------------
__global__ void zero_agg_kernel() {
    size_t i = (size_t)blockIdx.x * blockDim.x + threadIdx.x;
    size_t total4 = ((size_t)N_ENTITY * DIM) / 4;
    if (i < total4) ((float4*)g_agg)[i] = make_float4(0.f, 0.f, 0.f, 0.f);
}

// ---------------------------------------------------------------------------
// 5) scatter edges grouped by src
// ---------------------------------------------------------------------------
__global__ void scatter_kernel(const int* __restrict__ src,
                               const int* __restrict__ dst,
                               const int* __restrict__ typ) {
    int e = blockIdx.x * blockDim.x + threadIdx.x;
    if (e >= N_EDGES) return;
    int s = src[e];
    int pos = g_start[s] + atomicAdd(&g_cursor[s], 1);
    g_pack[pos] = dst[e] | (typ[e] << 20);
}

// ---------------------------------------------------------------------------
// 6) grouped aggregation: one warp per src; 8 basis rows live in registers.
// ---------------------------------------------------------------------------
__global__ void __launch_bounds__(256) agg_kernel(const float* __restrict__ basis,
                                                  const float* __restrict__ att) {
    __shared__ float4 att_s[N_REL * 2];
    for (int i = threadIdx.x; i < N_REL * 2; i += blockDim.x)
        att_s[i] = ((const float4*)att)[i];
    __syncthreads();

    int w = (int)((blockIdx.x * blockDim.x + threadIdx.x) >> 5);
    int lane = threadIdx.x & 31;
    if (w >= N_ENTITY) return;
    int cnt = g_hist[w];
    if (cnt == 0) return;
    int start = g_start[w];

    float4 r[N_BASES];
#pragma unroll
    for (int b = 0; b < N_BASES; b++)
        r[b] = __ldg((const float4*)(basis + ((size_t)b * N_ENTITY + (size_t)w) * DIM) + lane);

    for (int i0 = 0; i0 < cnt; i0 += 32) {
        int n = min(32, cnt - i0);
        int pk = 0;
        if (lane < n) pk = g_pack[start + i0 + lane];
        for (int i = 0; i < n; i++) {
            int p = __shfl_sync(0xffffffffu, pk, i);
            int d = p & 0xFFFFF;
            int t = p >> 20;
            float4 c0 = att_s[t * 2 + 0];
            float4 c1 = att_s[t * 2 + 1];
            float4 acc;
            acc.x = c0.x * r[0].x; acc.y = c0.x * r[0].y;
            acc.z = c0.x * r[0].z; acc.w = c0.x * r[0].w;
            acc.x = fmaf(c0.y, r[1].x, acc.x); acc.y = fmaf(c0.y, r[1].y, acc.y);
            acc.z = fmaf(c0.y, r[1].z, acc.z); acc.w = fmaf(c0.y, r[1].w, acc.w);
            acc.x = fmaf(c0.z, r[2].x, acc.x); acc.y = fmaf(c0.z, r[2].y, acc.y);
            acc.z = fmaf(c0.z, r[2].z, acc.z); acc.w = fmaf(c0.z, r[2].w, acc.w);
            acc.x = fmaf(c0.w, r[3].x, acc.x); acc.y = fmaf(c0.w, r[3].y, acc.y);
            acc.z = fmaf(c0.w, r[3].z, acc.z); acc.w = fmaf(c0.w, r[3].w, acc.w);
            acc.x = fmaf(c1.x, r[4].x, acc.x); acc.y = fmaf(c1.x, r[4].y, acc.y);
            acc.z = fmaf(c1.x, r[4].z, acc.z); acc.w = fmaf(c1.x, r[4].w, acc.w);
            acc.x = fmaf(c1.y, r[5].x, acc.x); acc.y = fmaf(c1.y, r[5].y, acc.y);
            acc.z = fmaf(c1.y, r[5].z, acc.z); acc.w = fmaf(c1.y, r[5].w, acc.w);
            acc.x = fmaf(c1.z, r[6].x, acc.x); acc.y = fmaf(c1.z, r[6].y, acc.y);
            acc.z = fmaf(c1.z, r[6].z, acc.z); acc.w = fmaf(c1.z, r[6].w, acc.w);
            acc.x = fmaf(c1.w, r[7].x, acc.x); acc.y = fmaf(c1.w, r[7].y, acc.y);
            acc.z = fmaf(c1.w, r[7].z, acc.z); acc.w = fmaf(c1.w, r[7].w, acc.w);

            float* outp = g_agg + (size_t)d * DIM + lane * 4;
            asm volatile("red.global.add.v4.f32 [%0], {%1, %2, %3, %4};"
                         :: "l"(outp), "f"(acc.x), "f"(acc.y), "f"(acc.z), "f"(acc.w)
                         : "memory");
        }
    }
}

// ---------------------------------------------------------------------------
// 7) attention pooling (finalize fused into the gather)
// ---------------------------------------------------------------------------
__global__ void attn_kernel(const int* __restrict__ seed_ids,
                            const float* __restrict__ A,
                            const float* __restrict__ bvec,
                            const float* __restrict__ root,
                            const float* __restrict__ rbias) {
    __shared__ float H[SEED_LEN][DIM + 1];
    __shared__ float e_s[SEED_LEN];
    __shared__ float attnw[SEED_LEN];

    int b = blockIdx.x;
    int tid = threadIdx.x;
    int lane = tid & 31, warp = tid >> 5;

    // gather H with fused finalize: node = agg/deg + root + bias
    for (int r = 0; r < SEED_LEN * DIM / 256; r++) {
        int idx = r * 256 + tid;
        int s = idx >> 7, d = idx & 127;
        int node = seed_ids[b * SEED_LEN + s];
        float invd = 1.0f / fmaxf(g_deg[node], 1.0f);
        H[s][d] = g_agg[(size_t)node * DIM + d] * invd +
                  __ldg(root + (size_t)node * DIM + d) + __ldg(rbias + d);
    }
    __syncthreads();

    float4 acc[4];
#pragma unroll
    for (int ss = 0; ss < 4; ss++) acc[ss] = make_float4(0.f, 0.f, 0.f, 0.f);
    int s0 = warp * 4;
#pragma unroll 4
    for (int k = 0; k < DIM; k++) {
        float4 a4 = __ldg((const float4*)(A + (size_t)k * DIM) + lane);
        float h0 = H[s0 + 0][k];
        float h1 = H[s0 + 1][k];
        float h2 = H[s0 + 2][k];
        float h3 = H[s0 + 3][k];
        acc[0].x = fmaf(h0, a4.x, acc[0].x); acc[0].y = fmaf(h0, a4.y, acc[0].y);
        acc[0].z = fmaf(h0, a4.z, acc[0].z); acc[0].w = fmaf(h0, a4.w, acc[0].w);
        acc[1].x = fmaf(h1, a4.x, acc[1].x); acc[1].y = fmaf(h1, a4.y, acc[1].y);
        acc[1].z = fmaf(h1, a4.z, acc[1].z); acc[1].w = fmaf(h1, a4.w, acc[1].w);
        acc[2].x = fmaf(h2, a4.x, acc[2].x); acc[2].y = fmaf(h2, a4.y, acc[2].y);
        acc[2].z = fmaf(h2, a4.z, acc[2].z); acc[2].w = fmaf(h2, a4.w, acc[2].w);
        acc[3].x = fmaf(h3, a4.x, acc[3].x); acc[3].y = fmaf(h3, a4.y, acc[3].y);
        acc[3].z = fmaf(h3, a4.z, acc[3].z); acc[3].w = fmaf(h3, a4.w, acc[3].w);
    }

    float4 b4 = __ldg((const float4*)bvec + lane);
#pragma unroll
    for (int ss = 0; ss < 4; ss++) {
        float v = tanhf(acc[ss].x) * b4.x + tanhf(acc[ss].y) * b4.y +
                  tanhf(acc[ss].z) * b4.z + tanhf(acc[ss].w) * b4.w;
#pragma unroll
        for (int o = 16; o > 0; o >>= 1) v += __shfl_xor_sync(0xffffffffu, v, o);
        if (lane == 0) e_s[s0 + ss] = v;
    }
    __syncthreads();

    if (warp == 0) {
        float ev = e_s[lane];
        float m = ev;
#pragma unroll
        for (int o = 16; o > 0; o >>= 1)
            m = fmaxf(m, __shfl_xor_sync(0xffffffffu, m, o));
        float ex = expf(ev - m);
        float ss2 = ex;
#pragma unroll
        for (int o = 16; o > 0; o >>= 1) ss2 += __shfl_xor_sync(0xffffffffu, ss2, o);
        attnw[lane] = ex / ss2;
    }
    __syncthreads();

    if (tid < DIM) {
        float u = 0.f;
#pragma unroll
        for (int s = 0; s < SEED_LEN; s++) u = fmaf(attnw[s], H[s][tid], u);
        g_u[b * DIM + tid] = u;
    }
}

// ---------------------------------------------------------------------------
// 8) scores with fused finalize: nodes computed on the fly from agg/deg/root
// ---------------------------------------------------------------------------
#define ETILE 64
#define KCH 64
__global__ void scores_kernel(const float* __restrict__ out_bias,
                              const float* __restrict__ root,
                              const float* __restrict__ rbias,
                              float* __restrict__ out) {
    __shared__ float nS[ETILE][KCH + 1];
    __shared__ float uS[BATCH][KCH + 1];
    __shared__ float invd_s[ETILE];
    int e0 = blockIdx.x * ETILE;
    int tid = threadIdx.x;
    int ti = tid & 15;
    int tj = tid >> 4;

    if (tid < ETILE) {
        int e = e0 + tid;
        invd_s[tid] = (e < N_ENTITY) ? 1.0f / fmaxf(g_deg[e], 1.0f) : 0.f;
    }

    float acc[4][4];
#pragma unroll
    for (int i = 0; i < 4; i++)
#pragma unroll
        for (int j = 0; j < 4; j++) acc[i][j] = 0.f;

    for (int kc = 0; kc < DIM; kc += KCH) {
        __syncthreads();
        // float4 loads: 64 rows x 16 float4 = 1024 per tile
        for (int q = tid; q < ETILE * (KCH / 4); q += 256) {
            int r = q >> 4;          // row
            int c4 = (q & 15) * 4;   // col (float)
            int e = e0 + r;
            float4 nv = make_float4(0.f, 0.f, 0.f, 0.f);
            if (e < N_ENTITY) {
                float4 a = *(const float4*)(g_agg + (size_t)e * DIM + kc + c4);
                float4 rt = __ldg((const float4*)(root + (size_t)e * DIM + kc + c4));
                float4 bb = __ldg((const float4*)(rbias + kc + c4));
                float iv = invd_s[r];
                nv.x = a.x * iv + rt.x + bb.x;
                nv.y = a.y * iv + rt.y + bb.y;
                nv.z = a.z * iv + rt.z + bb.z;
                nv.w = a.w * iv + rt.w + bb.w;
            }
            nS[r][c4 + 0] = nv.x; nS[r][c4 + 1] = nv.y;
            nS[r][c4 + 2] = nv.z; nS[r][c4 + 3] = nv.w;
            float4 uv = *(const float4*)(g_u + r * DIM + kc + c4);
            uS[r][c4 + 0] = uv.x; uS[r][c4 + 1] = uv.y;
            uS[r][c4 + 2] = uv.z; uS[r][c4 + 3] = uv.w;
        }
        __syncthreads();
#pragma unroll 8
        for (int k = 0; k < KCH; k++) {
            float nf[4], uf[4];
#pragma unroll
            for (int i = 0; i < 4; i++) nf[i] = nS[ti * 4 + i][k];
#pragma unroll
            for (int j = 0; j < 4; j++) uf[j] = uS[tj * 4 + j][k];
#pragma unroll
            for (int i = 0; i < 4; i++)
#pragma unroll
                for (int j = 0; j < 4; j++)
                    acc[i][j] = fmaf(nf[i], uf[j], acc[i][j]);
        }
    }

#pragma unroll
    for (int i = 0; i < 4; i++) {
        int e = e0 + ti * 4 + i;
        if (e >= N_ENTITY) continue;
        float ob = out_bias[e];
#pragma unroll
        for (int j = 0; j < 4; j++) {
            int bb = tj * 4 + j;
            out[(size_t)bb * N_ENTITY + e] = acc[i][j] + ob;
        }
    }
}

// ---------------------------------------------------------------------------
extern "C" void kernel_launch(void* const* d_in, const int* in_sizes, int n_in,
                              void* d_out, int out_size) {
    const int*   seed_ids = (const int*)d_in[0];
    const int*   edge_src = (const int*)d_in[1];
    const int*   edge_dst = (const int*)d_in[2];
    const int*   edge_typ = (const int*)d_in[3];
    const float* basis    = (const float*)d_in[4];
    const float* att      = (const float*)d_in[5];
    const float* root     = (const float*)d_in[6];
    const float* rbias    = (const float*)d_in[7];
    const float* attn_a   = (const float*)d_in[8];
    const float* attn_b   = (const float*)d_in[9];
    const float* out_bias = (const float*)d_in[10];
    float* out = (float*)d_out;

    zero_meta_kernel<<<(HIST_PAD + 255) / 256, 256>>>();                       // 1
    hist_kernel<<<(N_EDGES + 255) / 256, 256>>>(edge_src, edge_dst);           // 2
    scan_kernel<<<SCAN_NBLK, SCAN_BLK>>>();                                    // 3
    {
        size_t total4 = ((size_t)N_ENTITY * DIM) / 4;
        zero_agg_kernel<<<(int)((total4 + 255) / 256), 256>>>();               // 4
    }
    scatter_kernel<<<(N_EDGES + 255) / 256, 256>>>(edge_src, edge_dst, edge_typ); // 5
    agg_kernel<<<(N_ENTITY * 32 + 255) / 256, 256>>>(basis, att);              // 6 (ncu target)
    attn_kernel<<<BATCH, 256>>>(seed_ids, attn_a, attn_b, root, rbias);        // 7
    scores_kernel<<<(N_ENTITY + ETILE - 1) / ETILE, 256>>>(out_bias, root, rbias, out); // 8
}

// round 6
// speedup vs baseline: 2.0469x; 1.0002x over previous
#include <cuda_runtime.h>
#include <math.h>

#define N_ENTITY 64368
#define N_REL 40
#define DIM 128
#define N_BASES 8
#define N_EDGES 500000
#define BATCH 64
#define SEED_LEN 32

#define SCAN_BLK 1024
#define SCAN_NBLK 63            // 63*1024 = 64512 >= 64368
#define HIST_PAD (SCAN_NBLK * SCAN_BLK)

// ------------------------- device scratch (no allocs) ----------------------
// INVARIANT: g_agg, g_hist, g_cursor, g_deg, g_total are ZERO on entry to
// kernel_launch (zero-initialized at module load; cleanup_kernel restores
// zero at the end of every call). Same work every call -> deterministic.
__device__ float g_agg[(size_t)N_ENTITY * DIM];
__device__ float g_deg[N_ENTITY];
__device__ float g_u[BATCH * DIM];
__device__ int   g_hist[HIST_PAD];     // edge count per src
__device__ int   g_start[HIST_PAD];    // group start (contiguous, arbitrary order)
__device__ int   g_cursor[N_ENTITY];
__device__ int   g_total;
__device__ int   g_pack[N_EDGES];      // dst | (type<<20), grouped by src

// ---------------------------------------------------------------------------
// 1) histogram of src + degree of dst  (g_hist/g_deg are zero on entry)
// ---------------------------------------------------------------------------
__global__ void hist_kernel(const int* __restrict__ src,
                            const int* __restrict__ dst) {
    int e = blockIdx.x * blockDim.x + threadIdx.x;
    if (e >= N_EDGES) return;
    atomicAdd(&g_hist[src[e]], 1);
    atomicAdd(&g_deg[dst[e]], 1.0f);
}

// ---------------------------------------------------------------------------
// 2) single-pass offset allocation: block scan (shfl) + atomic block base.
// ---------------------------------------------------------------------------
__global__ void scan_kernel() {
    __shared__ int wsum[32];
    __shared__ int base_s;
    int t = threadIdx.x;
    int lane = t & 31, warp = t >> 5;
    int i = blockIdx.x * SCAN_BLK + t;
    int v = g_hist[i];

    int x = v;
#pragma unroll
    for (int o = 1; o < 32; o <<= 1) {
        int y = __shfl_up_sync(0xffffffffu, x, o);
        if (lane >= o) x += y;
    }
    if (lane == 31) wsum[warp] = x;
    __syncthreads();
    if (warp == 0) {
        int s = wsum[lane];
#pragma unroll
        for (int o = 1; o < 32; o <<= 1) {
            int y = __shfl_up_sync(0xffffffffu, s, o);
            if (lane >= o) s += y;
        }
        wsum[lane] = s;
    }
    __syncthreads();
    int incl = x + (warp ? wsum[warp - 1] : 0);
    if (t == SCAN_BLK - 1) base_s = atomicAdd(&g_total, incl);
    __syncthreads();
    g_start[i] = base_s + incl - v;
}

// ---------------------------------------------------------------------------
// 3) scatter edges grouped by src  (g_cursor zero on entry)
// ---------------------------------------------------------------------------
__global__ void scatter_kernel(const int* __restrict__ src,
                               const int* __restrict__ dst,
                               const int* __restrict__ typ) {
    int e = blockIdx.x * blockDim.x + threadIdx.x;
    if (e >= N_EDGES) return;
    int s = src[e];
    int pos = g_start[s] + atomicAdd(&g_cursor[s], 1);
    g_pack[pos] = dst[e] | (typ[e] << 20);
}

// ---------------------------------------------------------------------------
// 4) grouped aggregation (LAUNCH #4 -> ncu target). One warp per src.
//    f32x2 packed FMAs: 16 FFMA2 per edge-lane instead of 32 FFMA.
// ---------------------------------------------------------------------------
#define FMA2(acc, c, v) \
    asm("fma.rn.f32x2 %0, %1, %2, %0;" : "+l"(acc) : "l"(c), "l"(v))

__global__ void __launch_bounds__(256) agg_kernel(const float* __restrict__ basis,
                                                  const float* __restrict__ att) {
    // att coefficients duplicated into both f32x2 lanes: (c, c).
    // NOTE: 320 entries > 256 threads -> MUST be a strided loop.
    __shared__ __align__(16) unsigned long long att_dup[N_REL * N_BASES];
    int tid = threadIdx.x;
    for (int i = tid; i < N_REL * N_BASES; i += blockDim.x) {
        unsigned int ci = __float_as_uint(att[i]);
        att_dup[i] = ((unsigned long long)ci << 32) | (unsigned long long)ci;
    }
    __syncthreads();

    int w = (int)((blockIdx.x * blockDim.x + tid) >> 5);
    int lane = tid & 31;
    if (w >= N_ENTITY) return;
    int cnt = g_hist[w];
    if (cnt == 0) return;
    int start = g_start[w];

    // 8 basis rows, packed as f32x2 pairs (lo = dims 4l..4l+1, hi = 4l+2..4l+3)
    unsigned long long r0[N_BASES], r1[N_BASES];
#pragma unroll
    for (int b = 0; b < N_BASES; b++) {
        ulonglong2 v = __ldg(
            (const ulonglong2*)(basis + ((size_t)b * N_ENTITY + (size_t)w) * DIM) + lane);
        r0[b] = v.x;
        r1[b] = v.y;
    }

    float* base_out = g_agg + (size_t)lane * 4;

    for (int i0 = 0; i0 < cnt; i0 += 32) {
        int n = min(32, cnt - i0);
        int pk = 0;
        if (lane < n) pk = g_pack[start + i0 + lane];
        for (int i = 0; i < n; i++) {
            int p = __shfl_sync(0xffffffffu, pk, i);
            int d = p & 0xFFFFF;
            int t = p >> 20;
            const ulonglong2* ad = (const ulonglong2*)(att_dup + t * N_BASES);
            ulonglong2 q0 = ad[0];  // c0,c1
            ulonglong2 q1 = ad[1];  // c2,c3
            ulonglong2 q2 = ad[2];  // c4,c5
            ulonglong2 q3 = ad[3];  // c6,c7

            unsigned long long acc0 = 0ull, acc1 = 0ull;
            FMA2(acc0, q0.x, r0[0]); FMA2(acc1, q0.x, r1[0]);
            FMA2(acc0, q0.y, r0[1]); FMA2(acc1, q0.y, r1[1]);
            FMA2(acc0, q1.x, r0[2]); FMA2(acc1, q1.x, r1[2]);
            FMA2(acc0, q1.y, r0[3]); FMA2(acc1, q1.y, r1[3]);
            FMA2(acc0, q2.x, r0[4]); FMA2(acc1, q2.x, r1[4]);
            FMA2(acc0, q2.y, r0[5]); FMA2(acc1, q2.y, r1[5]);
            FMA2(acc0, q3.x, r0[6]); FMA2(acc1, q3.x, r1[6]);
            FMA2(acc0, q3.y, r0[7]); FMA2(acc1, q3.y, r1[7]);

            float a0 = __uint_as_float((unsigned int)acc0);
            float a1 = __uint_as_float((unsigned int)(acc0 >> 32));
            float a2 = __uint_as_float((unsigned int)acc1);
            float a3 = __uint_as_float((unsigned int)(acc1 >> 32));

            float* outp = base_out + (size_t)d * DIM;
            asm volatile("red.global.add.v4.f32 [%0], {%1, %2, %3, %4};"
                         :: "l"(outp), "f"(a0), "f"(a1), "f"(a2), "f"(a3)
                         : "memory");
        }
    }
}

// ---------------------------------------------------------------------------
// 5) attention pooling (finalize fused into the gather)
// ---------------------------------------------------------------------------
__global__ void attn_kernel(const int* __restrict__ seed_ids,
                            const float* __restrict__ A,
                            const float* __restrict__ bvec,
                            const float* __restrict__ root,
                            const float* __restrict__ rbias) {
    __shared__ float H[SEED_LEN][DIM + 1];
    __shared__ float e_s[SEED_LEN];
    __shared__ float attnw[SEED_LEN];

    int b = blockIdx.x;
    int tid = threadIdx.x;
    int lane = tid & 31, warp = tid >> 5;

    for (int r = 0; r < SEED_LEN * DIM / 256; r++) {
        int idx = r * 256 + tid;
        int s = idx >> 7, d = idx & 127;
        int node = seed_ids[b * SEED_LEN + s];
        float invd = 1.0f / fmaxf(g_deg[node], 1.0f);
        H[s][d] = g_agg[(size_t)node * DIM + d] * invd +
                  __ldg(root + (size_t)node * DIM + d) + __ldg(rbias + d);
    }
    __syncthreads();

    float4 acc[4];
#pragma unroll
    for (int ss = 0; ss < 4; ss++) acc[ss] = make_float4(0.f, 0.f, 0.f, 0.f);
    int s0 = warp * 4;
#pragma unroll 4
    for (int k = 0; k < DIM; k++) {
        float4 a4 = __ldg((const float4*)(A + (size_t)k * DIM) + lane);
        float h0 = H[s0 + 0][k];
        float h1 = H[s0 + 1][k];
        float h2 = H[s0 + 2][k];
        float h3 = H[s0 + 3][k];
        acc[0].x = fmaf(h0, a4.x, acc[0].x); acc[0].y = fmaf(h0, a4.y, acc[0].y);
        acc[0].z = fmaf(h0, a4.z, acc[0].z); acc[0].w = fmaf(h0, a4.w, acc[0].w);
        acc[1].x = fmaf(h1, a4.x, acc[1].x); acc[1].y = fmaf(h1, a4.y, acc[1].y);
        acc[1].z = fmaf(h1, a4.z, acc[1].z); acc[1].w = fmaf(h1, a4.w, acc[1].w);
        acc[2].x = fmaf(h2, a4.x, acc[2].x); acc[2].y = fmaf(h2, a4.y, acc[2].y);
        acc[2].z = fmaf(h2, a4.z, acc[2].z); acc[2].w = fmaf(h2, a4.w, acc[2].w);
        acc[3].x = fmaf(h3, a4.x, acc[3].x); acc[3].y = fmaf(h3, a4.y, acc[3].y);
        acc[3].z = fmaf(h3, a4.z, acc[3].z); acc[3].w = fmaf(h3, a4.w, acc[3].w);
    }

    float4 b4 = __ldg((const float4*)bvec + lane);
#pragma unroll
    for (int ss = 0; ss < 4; ss++) {
        float v = tanhf(acc[ss].x) * b4.x + tanhf(acc[ss].y) * b4.y +
                  tanhf(acc[ss].z) * b4.z + tanhf(acc[ss].w) * b4.w;
#pragma unroll
        for (int o = 16; o > 0; o >>= 1) v += __shfl_xor_sync(0xffffffffu, v, o);
        if (lane == 0) e_s[s0 + ss] = v;
    }
    __syncthreads();

    if (warp == 0) {
        float ev = e_s[lane];
        float m = ev;
#pragma unroll
        for (int o = 16; o > 0; o >>= 1)
            m = fmaxf(m, __shfl_xor_sync(0xffffffffu, m, o));
        float ex = expf(ev - m);
        float ss2 = ex;
#pragma unroll
        for (int o = 16; o > 0; o >>= 1) ss2 += __shfl_xor_sync(0xffffffffu, ss2, o);
        attnw[lane] = ex / ss2;
    }
    __syncthreads();

    if (tid < DIM) {
        float u = 0.f;
#pragma unroll
        for (int s = 0; s < SEED_LEN; s++) u = fmaf(attnw[s], H[s][tid], u);
        g_u[b * DIM + tid] = u;
    }
}

// ---------------------------------------------------------------------------
// 6) scores with fused finalize
// ---------------------------------------------------------------------------
#define ETILE 64
#define KCH 64
__global__ void scores_kernel(const float* __restrict__ out_bias,
                              const float* __restrict__ root,
                              const float* __restrict__ rbias,
                              float* __restrict__ out) {
    __shared__ float nS[ETILE][KCH + 1];
    __shared__ float uS[BATCH][KCH + 1];
    __shared__ float invd_s[ETILE];
    int e0 = blockIdx.x * ETILE;
    int tid = threadIdx.x;
    int ti = tid & 15;
    int tj = tid >> 4;

    if (tid < ETILE) {
        int e = e0 + tid;
        invd_s[tid] = (e < N_ENTITY) ? 1.0f / fmaxf(g_deg[e], 1.0f) : 0.f;
    }

    float acc[4][4];
#pragma unroll
    for (int i = 0; i < 4; i++)
#pragma unroll
        for (int j = 0; j < 4; j++) acc[i][j] = 0.f;

    for (int kc = 0; kc < DIM; kc += KCH) {
        __syncthreads();
        for (int q = tid; q < ETILE * (KCH / 4); q += 256) {
            int r = q >> 4;
            int c4 = (q & 15) * 4;
            int e = e0 + r;
            float4 nv = make_float4(0.f, 0.f, 0.f, 0.f);
            if (e < N_ENTITY) {
                float4 a = *(const float4*)(g_agg + (size_t)e * DIM + kc + c4);
                float4 rt = __ldg((const float4*)(root + (size_t)e * DIM + kc + c4));
                float4 bb = __ldg((const float4*)(rbias + kc + c4));
                float iv = invd_s[r];
                nv.x = a.x * iv + rt.x + bb.x;
                nv.y = a.y * iv + rt.y + bb.y;
                nv.z = a.z * iv + rt.z + bb.z;
                nv.w = a.w * iv + rt.w + bb.w;
            }
            nS[r][c4 + 0] = nv.x; nS[r][c4 + 1] = nv.y;
            nS[r][c4 + 2] = nv.z; nS[r][c4 + 3] = nv.w;
            float4 uv = *(const float4*)(g_u + r * DIM + kc + c4);
            uS[r][c4 + 0] = uv.x; uS[r][c4 + 1] = uv.y;
            uS[r][c4 + 2] = uv.z; uS[r][c4 + 3] = uv.w;
        }
        __syncthreads();
#pragma unroll 8
        for (int k = 0; k < KCH; k++) {
            float nf[4], uf[4];
#pragma unroll
            for (int i = 0; i < 4; i++) nf[i] = nS[ti * 4 + i][k];
#pragma unroll
            for (int j = 0; j < 4; j++) uf[j] = uS[tj * 4 + j][k];
#pragma unroll
            for (int i = 0; i < 4; i++)
#pragma unroll
                for (int j = 0; j < 4; j++)
                    acc[i][j] = fmaf(nf[i], uf[j], acc[i][j]);
        }
    }

#pragma unroll
    for (int i = 0; i < 4; i++) {
        int e = e0 + ti * 4 + i;
        if (e >= N_ENTITY) continue;
        float ob = out_bias[e];
#pragma unroll
        for (int j = 0; j < 4; j++) {
            int bb = tj * 4 + j;
            out[(size_t)bb * N_ENTITY + e] = acc[i][j] + ob;
        }
    }
}

// ---------------------------------------------------------------------------
// 7) cleanup: restore the zero-on-entry invariant for the next call
// ---------------------------------------------------------------------------
__global__ void cleanup_kernel() {
    size_t i = (size_t)blockIdx.x * blockDim.x + threadIdx.x;
    size_t total4 = ((size_t)N_ENTITY * DIM) / 4;
    if (i < total4) ((float4*)g_agg)[i] = make_float4(0.f, 0.f, 0.f, 0.f);
    if (i < HIST_PAD) g_hist[i] = 0;
    if (i < N_ENTITY) { g_deg[i] = 0.f; g_cursor[i] = 0; }
    if (i == 0) g_total = 0;
}

// ---------------------------------------------------------------------------
extern "C" void kernel_launch(void* const* d_in, const int* in_sizes, int n_in,
                              void* d_out, int out_size) {
    const int*   seed_ids = (const int*)d_in[0];
    const int*   edge_src = (const int*)d_in[1];
    const int*   edge_dst = (const int*)d_in[2];
    const int*   edge_typ = (const int*)d_in[3];
    const float* basis    = (const float*)d_in[4];
    const float* att      = (const float*)d_in[5];
    const float* root     = (const float*)d_in[6];
    const float* rbias    = (const float*)d_in[7];
    const float* attn_a   = (const float*)d_in[8];
    const float* attn_b   = (const float*)d_in[9];
    const float* out_bias = (const float*)d_in[10];
    float* out = (float*)d_out;

    hist_kernel<<<(N_EDGES + 255) / 256, 256>>>(edge_src, edge_dst);              // 1
    scan_kernel<<<SCAN_NBLK, SCAN_BLK>>>();                                       // 2
    scatter_kernel<<<(N_EDGES + 255) / 256, 256>>>(edge_src, edge_dst, edge_typ); // 3
    agg_kernel<<<(N_ENTITY * 32 + 255) / 256, 256>>>(basis, att);                 // 4 (ncu)
    attn_kernel<<<BATCH, 256>>>(seed_ids, attn_a, attn_b, root, rbias);           // 5
    scores_kernel<<<(N_ENTITY + ETILE - 1) / ETILE, 256>>>(out_bias, root, rbias, out); // 6
    {
        size_t total4 = ((size_t)N_ENTITY * DIM) / 4;
        cleanup_kernel<<<(int)((total4 + 255) / 256), 256>>>();                   // 7
    }
}